// round 1
// baseline (speedup 1.0000x reference)
#include <cuda_runtime.h>
#include <math.h>

#define Tn 8192   // B*S tokens
#define Sn 1024
#define Bn 8
#define Hn 8
#define Un 64
#define Dn 512
#define Fn 2048

// ---------------- scratch (device globals; no allocation allowed) ----------
__device__ float g_Q[(size_t)Hn * Tn * Un];   // [H][T][U]
__device__ float g_K[(size_t)Hn * Tn * Un];   // [H][T][U]
__device__ float g_V[(size_t)Hn * Tn * Dn];   // [H][T][D]
__device__ float g_S[(size_t)Hn * Bn * Sn * Sn]; // [H][B][S][S] scores/probs
__device__ float g_Ac[(size_t)Tn * Hn * Dn];  // concat attn [T][H*D]
__device__ float g_mha[(size_t)Tn * Dn];
__device__ float g_hb[(size_t)Tn * Dn];       // h = LN1(x + mha)
__device__ float g_f1[(size_t)Tn * Fn];
__device__ float g_f2[(size_t)Tn * Dn];

// ---------------- generic batched SGEMM -------------------------------------
// C = alpha * A @ op(B) (+bias) (opt relu), row-major.
// Batch index z -> (h = z / bdiv, b = z % bdiv); per-matrix offsets are
// affine in (h, b). Assumes M,N divisible by 64 and K divisible by 16,
// and all pointers/lds 16B-alignable (true for every call below).
#define TS 64
#define KT 16

template <bool TRANSB, bool BIAS, bool RELU>
__global__ __launch_bounds__(256) void gemm_kernel(
    const float* __restrict__ A, const float* __restrict__ Bm,
    const float* __restrict__ bias, float* __restrict__ C,
    int M, int N, int K, int lda, int ldb, int ldc,
    long long sAh, long long sAb, long long sBh, long long sBb,
    long long sCh, long long sCb, int bdiv, float alpha)
{
    int z = blockIdx.z;
    int h = z / bdiv, b = z % bdiv;
    const float* Ab = A + h * sAh + b * sAb;
    const float* Bb = Bm + h * sBh + b * sBb;
    float* Cb = C + h * sCh + b * sCb;

    __shared__ __align__(16) float As[KT][TS + 4];
    __shared__ __align__(16) float Bs[KT][TS + 4];

    int tx = threadIdx.x, ty = threadIdx.y;
    int tid = ty * 16 + tx;
    int m0 = blockIdx.y * TS, n0 = blockIdx.x * TS;

    int a_m = tid >> 2;          // 0..63
    int a_k4 = (tid & 3) * 4;    // 0,4,8,12

    float acc[4][4] = {};

    for (int k0 = 0; k0 < K; k0 += KT) {
        // A tile: 64 rows x 16 k, float4 per thread
        float4 av = *(const float4*)(Ab + (long long)(m0 + a_m) * lda + k0 + a_k4);
        As[a_k4 + 0][a_m] = av.x; As[a_k4 + 1][a_m] = av.y;
        As[a_k4 + 2][a_m] = av.z; As[a_k4 + 3][a_m] = av.w;
        if (TRANSB) {
            float4 bv = *(const float4*)(Bb + (long long)(n0 + a_m) * ldb + k0 + a_k4);
            Bs[a_k4 + 0][a_m] = bv.x; Bs[a_k4 + 1][a_m] = bv.y;
            Bs[a_k4 + 2][a_m] = bv.z; Bs[a_k4 + 3][a_m] = bv.w;
        } else {
            int b_n = tid & 63;
            int b_k = tid >> 6;  // 0..3
#pragma unroll
            for (int i = 0; i < 4; i++)
                Bs[b_k + i * 4][b_n] =
                    Bb[(long long)(k0 + b_k + i * 4) * ldb + n0 + b_n];
        }
        __syncthreads();
#pragma unroll
        for (int kk = 0; kk < KT; kk++) {
            float4 a = *(const float4*)&As[kk][ty * 4];
            float4 bq = *(const float4*)&Bs[kk][tx * 4];
            float ar[4] = {a.x, a.y, a.z, a.w};
            float br[4] = {bq.x, bq.y, bq.z, bq.w};
#pragma unroll
            for (int i = 0; i < 4; i++)
#pragma unroll
                for (int j = 0; j < 4; j++)
                    acc[i][j] += ar[i] * br[j];
        }
        __syncthreads();
    }

#pragma unroll
    for (int i = 0; i < 4; i++) {
        long long m = m0 + ty * 4 + i;
        float4 o;
        float v[4];
#pragma unroll
        for (int j = 0; j < 4; j++) {
            int n = n0 + tx * 4 + j;
            float t = acc[i][j] * alpha;
            if (BIAS) t += bias[n];
            if (RELU) t = fmaxf(t, 0.0f);
            v[j] = t;
        }
        o.x = v[0]; o.y = v[1]; o.z = v[2]; o.w = v[3];
        *(float4*)(Cb + m * ldc + n0 + tx * 4) = o;
    }
}

// ---------------- softmax over last dim (1024) -------------------------------
__global__ __launch_bounds__(256) void softmax_kernel(float* __restrict__ P)
{
    long long row = blockIdx.x;
    float4* p = reinterpret_cast<float4*>(P + row * Sn);
    int tid = threadIdx.x;
    float4 v = p[tid];
    __shared__ float red[256];
    float m = fmaxf(fmaxf(v.x, v.y), fmaxf(v.z, v.w));
    red[tid] = m;
    __syncthreads();
    for (int s = 128; s; s >>= 1) {
        if (tid < s) red[tid] = fmaxf(red[tid], red[tid + s]);
        __syncthreads();
    }
    float rmax = red[0];
    __syncthreads();
    v.x = expf(v.x - rmax); v.y = expf(v.y - rmax);
    v.z = expf(v.z - rmax); v.w = expf(v.w - rmax);
    red[tid] = v.x + v.y + v.z + v.w;
    __syncthreads();
    for (int s = 128; s; s >>= 1) {
        if (tid < s) red[tid] += red[tid + s];
        __syncthreads();
    }
    float inv = 1.0f / red[0];
    v.x *= inv; v.y *= inv; v.z *= inv; v.w *= inv;
    p[tid] = v;
}

// ---------------- residual add + LayerNorm (row = 512) ----------------------
__global__ __launch_bounds__(128) void add_ln_kernel(
    const float* __restrict__ X, const float* __restrict__ Y,
    const float* __restrict__ gamma, const float* __restrict__ beta,
    float* __restrict__ out)
{
    long long row = blockIdx.x;
    int tid = threadIdx.x;  // 128 threads * 4 = 512
    const float4* x4 = reinterpret_cast<const float4*>(X + row * Dn);
    const float4* y4 = reinterpret_cast<const float4*>(Y + row * Dn);
    float4 a = x4[tid], c = y4[tid];
    float v0 = a.x + c.x, v1 = a.y + c.y, v2 = a.z + c.z, v3 = a.w + c.w;
    __shared__ float rs[128], rq[128];
    rs[tid] = v0 + v1 + v2 + v3;
    rq[tid] = v0 * v0 + v1 * v1 + v2 * v2 + v3 * v3;
    __syncthreads();
    for (int s = 64; s; s >>= 1) {
        if (tid < s) { rs[tid] += rs[tid + s]; rq[tid] += rq[tid + s]; }
        __syncthreads();
    }
    float mean = rs[0] * (1.0f / Dn);
    float var = rq[0] * (1.0f / Dn) - mean * mean;
    float rstd = rsqrtf(var + 1e-3f);
    float4 g = reinterpret_cast<const float4*>(gamma)[tid];
    float4 bb = reinterpret_cast<const float4*>(beta)[tid];
    float4 o;
    o.x = g.x * (v0 - mean) * rstd + bb.x;
    o.y = g.y * (v1 - mean) * rstd + bb.y;
    o.z = g.z * (v2 - mean) * rstd + bb.z;
    o.w = g.w * (v3 - mean) * rstd + bb.w;
    reinterpret_cast<float4*>(out + row * Dn)[tid] = o;
}

// ---------------- launch --------------------------------------------------
extern "C" void kernel_launch(void* const* d_in, const int* in_sizes, int n_in,
                              void* d_out, int out_size)
{
    const float* x  = (const float*)d_in[0];
    const float* qw = (const float*)d_in[1];
    const float* kw = (const float*)d_in[2];
    const float* vw = (const float*)d_in[3];
    const float* lw = (const float*)d_in[4];
    const float* g1 = (const float*)d_in[5];
    const float* b1v= (const float*)d_in[6];
    const float* w1 = (const float*)d_in[7];
    const float* bb1= (const float*)d_in[8];
    const float* w2 = (const float*)d_in[9];
    const float* bb2= (const float*)d_in[10];
    const float* g2 = (const float*)d_in[11];
    const float* b2v= (const float*)d_in[12];
    float* out = (float*)d_out;

    float *Q, *K, *V, *S, *Ac, *mha, *hb, *f1, *f2;
    cudaGetSymbolAddress((void**)&Q,   g_Q);
    cudaGetSymbolAddress((void**)&K,   g_K);
    cudaGetSymbolAddress((void**)&V,   g_V);
    cudaGetSymbolAddress((void**)&S,   g_S);
    cudaGetSymbolAddress((void**)&Ac,  g_Ac);
    cudaGetSymbolAddress((void**)&mha, g_mha);
    cudaGetSymbolAddress((void**)&hb,  g_hb);
    cudaGetSymbolAddress((void**)&f1,  g_f1);
    cudaGetSymbolAddress((void**)&f2,  g_f2);

    dim3 blk(16, 16);
    float scale = 1.0f / sqrtf((float)Dn);

    // Q = X @ qw[h]  (per head): [8192,512]x[512,64] -> [H][T][U]
    gemm_kernel<false, false, false><<<dim3(1, Tn / 64, Hn), blk>>>(
        x, qw, nullptr, Q, Tn, Un, Dn, Dn, Un, Un,
        0, 0, (long long)Dn * Un, 0, (long long)Tn * Un, 0, 1, 1.0f);
    // K
    gemm_kernel<false, false, false><<<dim3(1, Tn / 64, Hn), blk>>>(
        x, kw, nullptr, K, Tn, Un, Dn, Dn, Un, Un,
        0, 0, (long long)Dn * Un, 0, (long long)Tn * Un, 0, 1, 1.0f);
    // V = X @ vw[h]: [8192,512]x[512,512] -> [H][T][D]
    gemm_kernel<false, false, false><<<dim3(Dn / 64, Tn / 64, Hn), blk>>>(
        x, vw, nullptr, V, Tn, Dn, Dn, Dn, Dn, Dn,
        0, 0, (long long)Dn * Dn, 0, (long long)Tn * Dn, 0, 1, 1.0f);

    // scores[h,b] = scale * Q_hb @ K_hb^T : [1024,64]x[1024,64]^T
    gemm_kernel<true, false, false><<<dim3(Sn / 64, Sn / 64, Hn * Bn), blk>>>(
        Q, K, nullptr, S, Sn, Sn, Un, Un, Un, Sn,
        (long long)Tn * Un, (long long)Sn * Un,
        (long long)Tn * Un, (long long)Sn * Un,
        (long long)Bn * Sn * Sn, (long long)Sn * Sn, Bn, scale);

    // softmax over 64*1024 rows of 1024
    softmax_kernel<<<Hn * Bn * Sn, 256>>>(S);

    // attn[h,b] = P_hb @ V_hb : [1024,1024]x[1024,512], written straight into
    // concat layout Ac[t, h*512+e]
    gemm_kernel<false, false, false><<<dim3(Dn / 64, Sn / 64, Hn * Bn), blk>>>(
        S, V, nullptr, Ac, Sn, Dn, Sn, Sn, Dn, Hn * Dn,
        (long long)Bn * Sn * Sn, (long long)Sn * Sn,
        (long long)Tn * Dn, (long long)Sn * Dn,
        (long long)Dn, (long long)Sn * Hn * Dn, Bn, 1.0f);

    // mha = Ac @ lw : [8192,4096]x[4096,512]
    gemm_kernel<false, false, false><<<dim3(Dn / 64, Tn / 64, 1), blk>>>(
        Ac, lw, nullptr, mha, Tn, Dn, Hn * Dn, Hn * Dn, Dn, Dn,
        0, 0, 0, 0, 0, 0, 1, 1.0f);

    // h = LN1(x + mha)
    add_ln_kernel<<<Tn, 128>>>(x, mha, g1, b1v, hb);

    // f1 = relu(h @ w1 + b1) : [8192,512]x[512,2048]
    gemm_kernel<false, true, true><<<dim3(Fn / 64, Tn / 64, 1), blk>>>(
        hb, w1, bb1, f1, Tn, Fn, Dn, Dn, Fn, Fn,
        0, 0, 0, 0, 0, 0, 1, 1.0f);

    // f2 = f1 @ w2 + b2 : [8192,2048]x[2048,512]
    gemm_kernel<false, true, false><<<dim3(Dn / 64, Tn / 64, 1), blk>>>(
        f1, w2, bb2, f2, Tn, Dn, Fn, Fn, Dn, Dn,
        0, 0, 0, 0, 0, 0, 1, 1.0f);

    // out = LN2(h + f2)
    add_ln_kernel<<<Tn, 128>>>(hb, f2, g2, b2v, out);
}

// round 4
// speedup vs baseline: 1.2459x; 1.2459x over previous
#include <cuda_runtime.h>
#include <cstdint>
#include <math.h>

#define Tn 8192   // B*S tokens
#define Sn 1024
#define Bn 8
#define Hn 8
#define Un 64
#define Dn 512
#define Fn 2048

// ---------------- scratch (device globals; no allocation allowed) ----------
__device__ float g_Q[(size_t)Hn * Tn * Un];   // [H][T][U]
__device__ float g_K[(size_t)Hn * Tn * Un];   // [H][T][U]
__device__ float g_V[(size_t)Hn * Tn * Dn];   // [H][T][D]
__device__ float g_S[(size_t)Hn * Bn * Sn * Sn]; // [H][B][S][S]
__device__ float g_Ac[(size_t)Tn * Hn * Dn];  // concat attn [T][H*D]
__device__ float g_mha[(size_t)Tn * Dn];
__device__ float g_hb[(size_t)Tn * Dn];
__device__ float g_f1[(size_t)Tn * Fn];
__device__ float g_f2[(size_t)Tn * Dn];

// ---------------- cp.async helpers -----------------------------------------
__device__ __forceinline__ void cp_async16(uint32_t saddr, const float* gptr) {
    asm volatile("cp.async.cg.shared.global [%0], [%1], 16;\n"
                 :: "r"(saddr), "l"(gptr));
}
__device__ __forceinline__ void cp_commit() {
    asm volatile("cp.async.commit_group;\n" ::);
}
__device__ __forceinline__ void cp_wait0() {
    asm volatile("cp.async.wait_group 0;\n" ::);
}

// ---------------- 128xTSN SGEMM, 8x(TSN/16) per thread, double-buffered -----
// C = alpha * A @ op(B) (+bias) (opt relu), row-major.
// batch z -> (h = z/bdiv, b = z%bdiv), affine offsets.
// M % 128 == 0, N % TSN == 0, K % 16 == 0 for all calls below.
#define KT 16
#define APAD 20

template <int TSN, bool TRANSB, bool BIAS, bool RELU>
__global__ __launch_bounds__(256, 2) void gemm2(
    const float* __restrict__ A, const float* __restrict__ Bm,
    const float* __restrict__ bias, float* __restrict__ C,
    int M, int N, int K, int lda, int ldb, int ldc,
    long long sAh, long long sAb, long long sBh, long long sBb,
    long long sCh, long long sCb, int bdiv, float alpha)
{
    constexpr int TN = TSN / 16;   // 4 or 8
    __shared__ __align__(16) float As[2][128 * APAD];
    __shared__ __align__(16) float Bs[2][KT * TSN];

    int z = blockIdx.z;
    int h = z / bdiv, b = z % bdiv;
    const float* Ab = A + h * sAh + b * sAb;
    const float* Bb = Bm + h * sBh + b * sBb;
    float* Cb = C + h * sCh + b * sCb;

    int tid = threadIdx.x;
    int tx = tid & 15, ty = tid >> 4;
    long long m0 = (long long)blockIdx.y * 128;
    int n0 = blockIdx.x * TSN;

    // A tile load: thread -> row am (0..127), k-offset ak (0 or 8), 2x float4
    int am = tid >> 1;
    int ak = (tid & 1) * 8;
    const float* Ag = Ab + (m0 + am) * lda + ak;
    uint32_t sA0 = (uint32_t)__cvta_generic_to_shared(&As[0][am * APAD + ak]);
    uint32_t sA1 = (uint32_t)__cvta_generic_to_shared(&As[1][am * APAD + ak]);

    // B tile (non-trans, row-major [K,N]): contiguous cp.async
    int br, bc;
    if (TSN == 128) { br = tid >> 4; bc = (tid & 15) * 8; }
    else           { br = tid >> 4; bc = (tid & 15) * 4; }
    const float* Bg = Bb + (long long)br * ldb + n0 + bc;
    uint32_t sB0 = (uint32_t)__cvta_generic_to_shared(&Bs[0][br * TSN + bc]);
    uint32_t sB1 = (uint32_t)__cvta_generic_to_shared(&Bs[1][br * TSN + bc]);

    // B tile (trans, row-major [N,K]): register-staged transpose
    int bn = tid & 127;          // n within tile
    int bk = (tid >> 7) * 8;     // 0 or 8
    const float* Btg = Bb + (long long)(n0 + bn) * ldb + bk;

    float acc[8][TN];
#pragma unroll
    for (int i = 0; i < 8; i++)
#pragma unroll
        for (int j = 0; j < TN; j++) acc[i][j] = 0.0f;

    int ktiles = K / KT;

    // ---- prologue: tile 0 into buffer 0 ----
    cp_async16(sA0, Ag);
    cp_async16(sA0 + 16, Ag + 4);
    if (!TRANSB) {
        cp_async16(sB0, Bg);
        if (TSN == 128) cp_async16(sB0 + 16, Bg + 4);
    } else {
        float4 r0 = *(const float4*)(Btg);
        float4 r1 = *(const float4*)(Btg + 4);
        Bs[0][(bk + 0) * TSN + bn] = r0.x; Bs[0][(bk + 1) * TSN + bn] = r0.y;
        Bs[0][(bk + 2) * TSN + bn] = r0.z; Bs[0][(bk + 3) * TSN + bn] = r0.w;
        Bs[0][(bk + 4) * TSN + bn] = r1.x; Bs[0][(bk + 5) * TSN + bn] = r1.y;
        Bs[0][(bk + 6) * TSN + bn] = r1.z; Bs[0][(bk + 7) * TSN + bn] = r1.w;
    }
    cp_commit();

    for (int kt = 0; kt < ktiles; kt++) {
        int cur = kt & 1;
        cp_wait0();
        __syncthreads();

        bool has_next = (kt + 1) < ktiles;
        float4 nb0, nb1;
        if (has_next) {
            int kn = kt + 1;
            // next tile goes into buffer cur^1: cur==0 -> buf1, cur==1 -> buf0
            uint32_t sa = cur ? sA0 : sA1;
            cp_async16(sa, Ag + (long long)kn * KT);
            cp_async16(sa + 16, Ag + (long long)kn * KT + 4);
            if (!TRANSB) {
                uint32_t sb = cur ? sB0 : sB1;
                const float* g = Bg + (long long)kn * KT * ldb;
                cp_async16(sb, g);
                if (TSN == 128) cp_async16(sb + 16, g + 4);
            } else {
                nb0 = *(const float4*)(Btg + (long long)kn * KT);
                nb1 = *(const float4*)(Btg + (long long)kn * KT + 4);
            }
            cp_commit();
        }

        // ---- compute 16 k-steps from buffer cur ----
        const float* Ac_ = As[cur];
        const float* Bc_ = Bs[cur];
#pragma unroll
        for (int kk = 0; kk < KT; kk++) {
            float a[8];
#pragma unroll
            for (int i = 0; i < 4; i++) {
                a[i]     = Ac_[(ty * 4 + i) * APAD + kk];
                a[4 + i] = Ac_[(64 + ty * 4 + i) * APAD + kk];
            }
            float4 b0 = *(const float4*)&Bc_[kk * TSN + tx * 4];
            float br_[8];
            br_[0] = b0.x; br_[1] = b0.y; br_[2] = b0.z; br_[3] = b0.w;
            if (TN == 8) {
                float4 b1 = *(const float4*)&Bc_[kk * TSN + 64 + tx * 4];
                br_[4] = b1.x; br_[5] = b1.y; br_[6] = b1.z; br_[7] = b1.w;
            }
#pragma unroll
            for (int i = 0; i < 8; i++)
#pragma unroll
                for (int j = 0; j < TN; j++)
                    acc[i][j] += a[i] * br_[j];
        }

        if (TRANSB && has_next) {
            int nxt = cur ^ 1;
            Bs[nxt][(bk + 0) * TSN + bn] = nb0.x; Bs[nxt][(bk + 1) * TSN + bn] = nb0.y;
            Bs[nxt][(bk + 2) * TSN + bn] = nb0.z; Bs[nxt][(bk + 3) * TSN + bn] = nb0.w;
            Bs[nxt][(bk + 4) * TSN + bn] = nb1.x; Bs[nxt][(bk + 5) * TSN + bn] = nb1.y;
            Bs[nxt][(bk + 6) * TSN + bn] = nb1.z; Bs[nxt][(bk + 7) * TSN + bn] = nb1.w;
        }
    }

    // ---- epilogue ----
    float bv[TN];
    if (BIAS) {
#pragma unroll
        for (int jh = 0; jh < TN / 4; jh++)
#pragma unroll
            for (int j = 0; j < 4; j++)
                bv[jh * 4 + j] = bias[n0 + jh * 64 + tx * 4 + j];
    }
#pragma unroll
    for (int i = 0; i < 8; i++) {
        long long m = m0 + (i < 4 ? ty * 4 + i : 64 + ty * 4 + (i - 4));
#pragma unroll
        for (int jh = 0; jh < TN / 4; jh++) {
            float v[4];
#pragma unroll
            for (int j = 0; j < 4; j++) {
                float t = acc[i][jh * 4 + j] * alpha;
                if (BIAS) t += bv[jh * 4 + j];
                if (RELU) t = fmaxf(t, 0.0f);
                v[j] = t;
            }
            float4 o; o.x = v[0]; o.y = v[1]; o.z = v[2]; o.w = v[3];
            *(float4*)(Cb + m * ldc + n0 + jh * 64 + tx * 4) = o;
        }
    }
}

// ---------------- softmax over last dim (1024) -------------------------------
__global__ __launch_bounds__(256) void softmax_kernel(float* __restrict__ P)
{
    long long row = blockIdx.x;
    float4* p = reinterpret_cast<float4*>(P + row * Sn);
    int tid = threadIdx.x;
    float4 v = p[tid];
    __shared__ float red[256];
    float m = fmaxf(fmaxf(v.x, v.y), fmaxf(v.z, v.w));
    red[tid] = m;
    __syncthreads();
    for (int s = 128; s; s >>= 1) {
        if (tid < s) red[tid] = fmaxf(red[tid], red[tid + s]);
        __syncthreads();
    }
    float rmax = red[0];
    __syncthreads();
    v.x = expf(v.x - rmax); v.y = expf(v.y - rmax);
    v.z = expf(v.z - rmax); v.w = expf(v.w - rmax);
    red[tid] = v.x + v.y + v.z + v.w;
    __syncthreads();
    for (int s = 128; s; s >>= 1) {
        if (tid < s) red[tid] += red[tid + s];
        __syncthreads();
    }
    float inv = 1.0f / red[0];
    v.x *= inv; v.y *= inv; v.z *= inv; v.w *= inv;
    p[tid] = v;
}

// ---------------- residual add + LayerNorm (row = 512) ----------------------
__global__ __launch_bounds__(128) void add_ln_kernel(
    const float* __restrict__ X, const float* __restrict__ Y,
    const float* __restrict__ gamma, const float* __restrict__ beta,
    float* __restrict__ out)
{
    long long row = blockIdx.x;
    int tid = threadIdx.x;
    const float4* x4 = reinterpret_cast<const float4*>(X + row * Dn);
    const float4* y4 = reinterpret_cast<const float4*>(Y + row * Dn);
    float4 a = x4[tid], c = y4[tid];
    float v0 = a.x + c.x, v1 = a.y + c.y, v2 = a.z + c.z, v3 = a.w + c.w;
    __shared__ float rs[128], rq[128];
    rs[tid] = v0 + v1 + v2 + v3;
    rq[tid] = v0 * v0 + v1 * v1 + v2 * v2 + v3 * v3;
    __syncthreads();
    for (int s = 64; s; s >>= 1) {
        if (tid < s) { rs[tid] += rs[tid + s]; rq[tid] += rq[tid + s]; }
        __syncthreads();
    }
    float mean = rs[0] * (1.0f / Dn);
    float var = rq[0] * (1.0f / Dn) - mean * mean;
    float rstd = rsqrtf(var + 1e-3f);
    float4 g = reinterpret_cast<const float4*>(gamma)[tid];
    float4 bb = reinterpret_cast<const float4*>(beta)[tid];
    float4 o;
    o.x = g.x * (v0 - mean) * rstd + bb.x;
    o.y = g.y * (v1 - mean) * rstd + bb.y;
    o.z = g.z * (v2 - mean) * rstd + bb.z;
    o.w = g.w * (v3 - mean) * rstd + bb.w;
    reinterpret_cast<float4*>(out + row * Dn)[tid] = o;
}

// ---------------- launch --------------------------------------------------
extern "C" void kernel_launch(void* const* d_in, const int* in_sizes, int n_in,
                              void* d_out, int out_size)
{
    const float* x  = (const float*)d_in[0];
    const float* qw = (const float*)d_in[1];
    const float* kw = (const float*)d_in[2];
    const float* vw = (const float*)d_in[3];
    const float* lw = (const float*)d_in[4];
    const float* g1 = (const float*)d_in[5];
    const float* b1v= (const float*)d_in[6];
    const float* w1 = (const float*)d_in[7];
    const float* bb1= (const float*)d_in[8];
    const float* w2 = (const float*)d_in[9];
    const float* bb2= (const float*)d_in[10];
    const float* g2 = (const float*)d_in[11];
    const float* b2v= (const float*)d_in[12];
    float* out = (float*)d_out;

    float *Q, *K, *V, *S, *Ac, *mha, *hb, *f1, *f2;
    cudaGetSymbolAddress((void**)&Q,   g_Q);
    cudaGetSymbolAddress((void**)&K,   g_K);
    cudaGetSymbolAddress((void**)&V,   g_V);
    cudaGetSymbolAddress((void**)&S,   g_S);
    cudaGetSymbolAddress((void**)&Ac,  g_Ac);
    cudaGetSymbolAddress((void**)&mha, g_mha);
    cudaGetSymbolAddress((void**)&hb,  g_hb);
    cudaGetSymbolAddress((void**)&f1,  g_f1);
    cudaGetSymbolAddress((void**)&f2,  g_f2);

    float scale = 1.0f / sqrtf((float)Dn);

    // Q = X @ qw[h] : M=8192, N=64, K=512, batch H
    gemm2<64, false, false, false><<<dim3(1, Tn / 128, Hn), 256>>>(
        x, qw, nullptr, Q, Tn, Un, Dn, Dn, Un, Un,
        0, 0, (long long)Dn * Un, 0, (long long)Tn * Un, 0, 1, 1.0f);
    gemm2<64, false, false, false><<<dim3(1, Tn / 128, Hn), 256>>>(
        x, kw, nullptr, K, Tn, Un, Dn, Dn, Un, Un,
        0, 0, (long long)Dn * Un, 0, (long long)Tn * Un, 0, 1, 1.0f);
    // V = X @ vw[h] : M=8192, N=512, K=512, batch H
    gemm2<128, false, false, false><<<dim3(Dn / 128, Tn / 128, Hn), 256>>>(
        x, vw, nullptr, V, Tn, Dn, Dn, Dn, Dn, Dn,
        0, 0, (long long)Dn * Dn, 0, (long long)Tn * Dn, 0, 1, 1.0f);

    // scores[h,b] = scale * Q_hb @ K_hb^T : M=N=1024, K=64, batch H*B
    gemm2<128, true, false, false><<<dim3(Sn / 128, Sn / 128, Hn * Bn), 256>>>(
        Q, K, nullptr, S, Sn, Sn, Un, Un, Un, Sn,
        (long long)Tn * Un, (long long)Sn * Un,
        (long long)Tn * Un, (long long)Sn * Un,
        (long long)Bn * Sn * Sn, (long long)Sn * Sn, Bn, scale);

    softmax_kernel<<<Hn * Bn * Sn, 256>>>(S);

    // attn[h,b] = P_hb @ V_hb -> concat layout Ac[t, h*512+e]
    gemm2<128, false, false, false><<<dim3(Dn / 128, Sn / 128, Hn * Bn), 256>>>(
        S, V, nullptr, Ac, Sn, Dn, Sn, Sn, Dn, Hn * Dn,
        (long long)Bn * Sn * Sn, (long long)Sn * Sn,
        (long long)Tn * Dn, (long long)Sn * Dn,
        (long long)Dn, (long long)Sn * Hn * Dn, Bn, 1.0f);

    // mha = Ac @ lw : M=8192, N=512, K=4096
    gemm2<128, false, false, false><<<dim3(Dn / 128, Tn / 128, 1), 256>>>(
        Ac, lw, nullptr, mha, Tn, Dn, Hn * Dn, Hn * Dn, Dn, Dn,
        0, 0, 0, 0, 0, 0, 1, 1.0f);

    add_ln_kernel<<<Tn, 128>>>(x, mha, g1, b1v, hb);

    // f1 = relu(h @ w1 + b1) : M=8192, N=2048, K=512
    gemm2<128, false, true, true><<<dim3(Fn / 128, Tn / 128, 1), 256>>>(
        hb, w1, bb1, f1, Tn, Fn, Dn, Dn, Fn, Fn,
        0, 0, 0, 0, 0, 0, 1, 1.0f);

    // f2 = f1 @ w2 + b2 : M=8192, N=512, K=2048
    gemm2<128, false, true, false><<<dim3(Dn / 128, Tn / 128, 1), 256>>>(
        f1, w2, bb2, f2, Tn, Dn, Fn, Fn, Dn, Dn,
        0, 0, 0, 0, 0, 0, 1, 1.0f);

    add_ln_kernel<<<Tn, 128>>>(hb, f2, g2, b2v, out);
}

// round 6
// speedup vs baseline: 2.4693x; 1.9819x over previous
#include <cuda_runtime.h>
#include <cuda_bf16.h>
#include <cstdint>
#include <math.h>

#define Tn 8192
#define Sn 1024
#define Bn 8
#define Hn 8
#define Un 64
#define Dn 512
#define Fn 2048

// ---------------- scratch ---------------------------------------------------
__device__ float g_Q[(size_t)Hn * Tn * Un];
__device__ float g_K[(size_t)Hn * Tn * Un];
__device__ float g_VT[(size_t)Hn * Dn * Tn];      // [H][D][T]
__device__ float g_S[(size_t)Hn * Bn * Sn * Sn];
__device__ float g_Ac[(size_t)Tn * Hn * Dn];
__device__ float g_mha[(size_t)Tn * Dn];
__device__ float g_hb[(size_t)Tn * Dn];
__device__ float g_f1[(size_t)Tn * Fn];
__device__ float g_f2[(size_t)Tn * Dn];
__device__ float g_qwT[(size_t)Hn * Un * Dn];
__device__ float g_kwT[(size_t)Hn * Un * Dn];
__device__ float g_vwT[(size_t)Hn * Dn * Dn];
__device__ float g_lwT[(size_t)Dn * Hn * Dn];
__device__ float g_w1T[(size_t)Fn * Dn];
__device__ float g_w2T[(size_t)Dn * Fn];

// ---------------- helpers ----------------------------------------------------
__device__ __forceinline__ uint32_t smem_u32(const void* p) {
    uint32_t a;
    asm("{ .reg .u64 t; cvta.to.shared.u64 t, %1; cvt.u32.u64 %0, t; }"
        : "=r"(a) : "l"(p));
    return a;
}
__device__ __forceinline__ void ldsm4(uint32_t* r, uint32_t addr) {
    asm volatile("ldmatrix.sync.aligned.m8n8.x4.shared.b16 {%0,%1,%2,%3}, [%4];"
                 : "=r"(r[0]), "=r"(r[1]), "=r"(r[2]), "=r"(r[3]) : "r"(addr));
}
__device__ __forceinline__ void mma16816(float* c, const uint32_t* a,
                                         uint32_t b0, uint32_t b1) {
    asm volatile(
        "mma.sync.aligned.m16n8k16.row.col.f32.bf16.bf16.f32 "
        "{%0,%1,%2,%3}, {%4,%5,%6,%7}, {%8,%9}, {%0,%1,%2,%3};"
        : "+f"(c[0]), "+f"(c[1]), "+f"(c[2]), "+f"(c[3])
        : "r"(a[0]), "r"(a[1]), "r"(a[2]), "r"(a[3]), "r"(b0), "r"(b1));
}
__device__ __forceinline__ void cvt_split(float4 v, uint2& h, uint2& l) {
    __nv_bfloat162 h0 = __floats2bfloat162_rn(v.x, v.y);
    __nv_bfloat162 h1 = __floats2bfloat162_rn(v.z, v.w);
    float2 f0 = __bfloat1622float2(h0);
    float2 f1 = __bfloat1622float2(h1);
    __nv_bfloat162 l0 = __floats2bfloat162_rn(v.x - f0.x, v.y - f0.y);
    __nv_bfloat162 l1 = __floats2bfloat162_rn(v.z - f1.x, v.w - f1.y);
    h.x = *(uint32_t*)&h0; h.y = *(uint32_t*)&h1;
    l.x = *(uint32_t*)&l0; l.y = *(uint32_t*)&l1;
}

// ---------------- bf16-split tensor GEMM ------------------------------------
// C[m,n] = alpha * sum_k A[m,k]*B[n,k] (+bias[n]) (opt relu).
// A row-major [M,K] lda, B row-major [N,K] ldb. M%128==0, N%TSN==0, K%16==0.
// 256 threads, warp grid 2(m)x4(n): warp tile 64 x TSN/4.
template <int TSN, bool BIAS, bool RELU>
__global__ __launch_bounds__(256) void mgemm(
    const float* __restrict__ A, const float* __restrict__ Bm,
    const float* __restrict__ bias, float* __restrict__ C,
    int M, int N, int K, int lda, int ldb, int ldc,
    long long sAh, long long sAb, long long sBh, long long sBb,
    long long sCh, long long sCb, int bdiv, float alpha)
{
    constexpr int WN = TSN / 4;       // n per warp (32 or 16)
    constexpr int NT = WN / 8;        // n8 tiles per warp (4 or 2)
    constexpr int NB = TSN / 64;      // B-load iterations (2 or 1)
    constexpr int ABYT = 128 * 48;    // 6144 bytes per (hi or lo) A chunk
    constexpr int BBYT = TSN * 48;
    constexpr int BUF = 2 * ABYT + 2 * BBYT;

    extern __shared__ char sm[];
    uint32_t sb = smem_u32(sm);

    int tid = threadIdx.x, lane = tid & 31, wid = tid >> 5;
    int wm = wid & 1, wn = wid >> 1;

    int z = blockIdx.z;
    int h = z / bdiv, b = z % bdiv;
    const float* Ag = A + h * sAh + b * sAb;
    const float* Bg = Bm + h * sBh + b * sBb;
    float* Cb = C + h * sCh + b * sCb;

    long long m0 = (long long)blockIdx.y * 128;
    int n0 = blockIdx.x * TSN;

    // global->smem staging mapping
    int lr = tid >> 2;                // 0..63
    int k4 = (tid & 3) * 4;           // 0,4,8,12
    const float* gA = Ag + (m0 + lr) * (long long)lda + k4;
    const float* gB = Bg + (long long)(n0 + lr) * ldb + k4;
    char* pAst = sm + lr * 48 + k4 * 2;
    char* pBst = sm + 2 * ABYT + lr * 48 + k4 * 2;

    // ldmatrix addressing
    int lrow = lane & 15, lhalf = lane >> 4;
    uint32_t ldA = sb + (wm * 64 + lrow) * 48 + lhalf * 16;
    uint32_t ldB = sb + 2 * ABYT + (wn * WN + lrow) * 48 + lhalf * 16;

    float acc[4][NT][4];
#pragma unroll
    for (int i = 0; i < 4; i++)
#pragma unroll
        for (int j = 0; j < NT; j++)
#pragma unroll
            for (int q = 0; q < 4; q++) acc[i][j][q] = 0.0f;

    int ktiles = K / 16;
    float4 ra[2], rb[NB];
#pragma unroll
    for (int i = 0; i < 2; i++)
        ra[i] = *(const float4*)(gA + (long long)i * 64 * lda);
#pragma unroll
    for (int i = 0; i < NB; i++)
        rb[i] = *(const float4*)(gB + (long long)i * 64 * ldb);

    for (int kt = 0; kt < ktiles; kt++) {
        uint32_t bo = (uint32_t)(kt & 1) * BUF;

        // convert + store staged regs
        {
            uint2 hh, ll;
            char* ab = pAst + bo;
#pragma unroll
            for (int i = 0; i < 2; i++) {
                cvt_split(ra[i], hh, ll);
                *(uint2*)(ab + i * 64 * 48) = hh;
                *(uint2*)(ab + i * 64 * 48 + ABYT) = ll;
            }
            char* bbp = pBst + bo;
#pragma unroll
            for (int i = 0; i < NB; i++) {
                cvt_split(rb[i], hh, ll);
                *(uint2*)(bbp + i * 64 * 48) = hh;
                *(uint2*)(bbp + i * 64 * 48 + BBYT) = ll;
            }
        }
        __syncthreads();

        if (kt + 1 < ktiles) {
            long long ko = (long long)(kt + 1) * 16;
#pragma unroll
            for (int i = 0; i < 2; i++)
                ra[i] = *(const float4*)(gA + (long long)i * 64 * lda + ko);
#pragma unroll
            for (int i = 0; i < NB; i++)
                rb[i] = *(const float4*)(gB + (long long)i * 64 * ldb + ko);
        }

        // 3 product terms: Ah*Bh, Al*Bh, Ah*Bl
#pragma unroll
        for (int t = 0; t < 3; t++) {
            uint32_t aoff = (t == 1) ? (uint32_t)ABYT : 0u;
            uint32_t boff = (t == 2) ? (uint32_t)BBYT : 0u;
            uint32_t af[4][4];
#pragma unroll
            for (int mt = 0; mt < 4; mt++)
                ldsm4(af[mt], ldA + bo + aoff + mt * 16 * 48);
#pragma unroll
            for (int np = 0; np < NT / 2; np++) {
                uint32_t bf[4];
                ldsm4(bf, ldB + bo + boff + np * 16 * 48);
#pragma unroll
                for (int mt = 0; mt < 4; mt++) {
                    mma16816(acc[mt][2 * np], af[mt], bf[0], bf[2]);
                    mma16816(acc[mt][2 * np + 1], af[mt], bf[1], bf[3]);
                }
            }
        }
        // note: next iteration's store targets the other buffer; the single
        // __syncthreads above orders compute(kt-1) vs store(kt+1).
    }

    // epilogue
    int g = lane >> 2, c2 = (lane & 3) * 2;
#pragma unroll
    for (int mt = 0; mt < 4; mt++) {
        long long r0 = m0 + wm * 64 + mt * 16 + g;
#pragma unroll
        for (int nt = 0; nt < NT; nt++) {
            int col = n0 + wn * WN + nt * 8 + c2;
            float v0 = acc[mt][nt][0] * alpha, v1 = acc[mt][nt][1] * alpha;
            float v2 = acc[mt][nt][2] * alpha, v3 = acc[mt][nt][3] * alpha;
            if (BIAS) {
                float b0 = bias[col], b1 = bias[col + 1];
                v0 += b0; v1 += b1; v2 += b0; v3 += b1;
            }
            if (RELU) {
                v0 = fmaxf(v0, 0.f); v1 = fmaxf(v1, 0.f);
                v2 = fmaxf(v2, 0.f); v3 = fmaxf(v3, 0.f);
            }
            float2 o0 = {v0, v1}, o1 = {v2, v3};
            *(float2*)(Cb + r0 * ldc + col) = o0;
            *(float2*)(Cb + (r0 + 8) * ldc + col) = o1;
        }
    }
}

// ---------------- transpose [Z][R][C] -> [Z][C][R] ---------------------------
__global__ __launch_bounds__(256) void transpose_kernel(
    const float* __restrict__ in, float* __restrict__ out, int R, int C)
{
    __shared__ float t[32][33];
    const float* ib = in + (long long)blockIdx.z * R * C;
    float* ob = out + (long long)blockIdx.z * R * C;
    int c0 = blockIdx.x * 32, r0 = blockIdx.y * 32;
    int x = threadIdx.x, y = threadIdx.y;
#pragma unroll
    for (int i = 0; i < 32; i += 8)
        t[y + i][x] = ib[(long long)(r0 + y + i) * C + c0 + x];
    __syncthreads();
#pragma unroll
    for (int i = 0; i < 32; i += 8)
        ob[(long long)(c0 + y + i) * R + r0 + x] = t[x][y + i];
}

// ---------------- softmax over last dim (1024) -------------------------------
__global__ __launch_bounds__(256) void softmax_kernel(float* __restrict__ P)
{
    long long row = blockIdx.x;
    float4* p = reinterpret_cast<float4*>(P + row * Sn);
    int tid = threadIdx.x;
    float4 v = p[tid];
    __shared__ float red[256];
    float m = fmaxf(fmaxf(v.x, v.y), fmaxf(v.z, v.w));
    red[tid] = m;
    __syncthreads();
    for (int s = 128; s; s >>= 1) {
        if (tid < s) red[tid] = fmaxf(red[tid], red[tid + s]);
        __syncthreads();
    }
    float rmax = red[0];
    __syncthreads();
    v.x = expf(v.x - rmax); v.y = expf(v.y - rmax);
    v.z = expf(v.z - rmax); v.w = expf(v.w - rmax);
    red[tid] = v.x + v.y + v.z + v.w;
    __syncthreads();
    for (int s = 128; s; s >>= 1) {
        if (tid < s) red[tid] += red[tid + s];
        __syncthreads();
    }
    float inv = 1.0f / red[0];
    v.x *= inv; v.y *= inv; v.z *= inv; v.w *= inv;
    p[tid] = v;
}

// ---------------- residual add + LayerNorm (row = 512) ----------------------
__global__ __launch_bounds__(128) void add_ln_kernel(
    const float* __restrict__ X, const float* __restrict__ Y,
    const float* __restrict__ gamma, const float* __restrict__ beta,
    float* __restrict__ out)
{
    long long row = blockIdx.x;
    int tid = threadIdx.x;
    const float4* x4 = reinterpret_cast<const float4*>(X + row * Dn);
    const float4* y4 = reinterpret_cast<const float4*>(Y + row * Dn);
    float4 a = x4[tid], c = y4[tid];
    float v0 = a.x + c.x, v1 = a.y + c.y, v2 = a.z + c.z, v3 = a.w + c.w;
    __shared__ float rs[128], rq[128];
    rs[tid] = v0 + v1 + v2 + v3;
    rq[tid] = v0 * v0 + v1 * v1 + v2 * v2 + v3 * v3;
    __syncthreads();
    for (int s = 64; s; s >>= 1) {
        if (tid < s) { rs[tid] += rs[tid + s]; rq[tid] += rq[tid + s]; }
        __syncthreads();
    }
    float mean = rs[0] * (1.0f / Dn);
    float var = rq[0] * (1.0f / Dn) - mean * mean;
    float rstd = rsqrtf(var + 1e-3f);
    float4 g = reinterpret_cast<const float4*>(gamma)[tid];
    float4 bb = reinterpret_cast<const float4*>(beta)[tid];
    float4 o;
    o.x = g.x * (v0 - mean) * rstd + bb.x;
    o.y = g.y * (v1 - mean) * rstd + bb.y;
    o.z = g.z * (v2 - mean) * rstd + bb.z;
    o.w = g.w * (v3 - mean) * rstd + bb.w;
    reinterpret_cast<float4*>(out + row * Dn)[tid] = o;
}

// ---------------- launch --------------------------------------------------
extern "C" void kernel_launch(void* const* d_in, const int* in_sizes, int n_in,
                              void* d_out, int out_size)
{
    const float* x  = (const float*)d_in[0];
    const float* qw = (const float*)d_in[1];
    const float* kw = (const float*)d_in[2];
    const float* vw = (const float*)d_in[3];
    const float* lw = (const float*)d_in[4];
    const float* g1 = (const float*)d_in[5];
    const float* b1v= (const float*)d_in[6];
    const float* w1 = (const float*)d_in[7];
    const float* bb1= (const float*)d_in[8];
    const float* w2 = (const float*)d_in[9];
    const float* bb2= (const float*)d_in[10];
    const float* g2 = (const float*)d_in[11];
    const float* b2v= (const float*)d_in[12];
    float* out = (float*)d_out;

    float *Q, *K, *VT, *S, *Ac, *mha, *hb, *f1, *f2;
    float *qwT, *kwT, *vwT, *lwT, *w1T, *w2T;
    cudaGetSymbolAddress((void**)&Q,   g_Q);
    cudaGetSymbolAddress((void**)&K,   g_K);
    cudaGetSymbolAddress((void**)&VT,  g_VT);
    cudaGetSymbolAddress((void**)&S,   g_S);
    cudaGetSymbolAddress((void**)&Ac,  g_Ac);
    cudaGetSymbolAddress((void**)&mha, g_mha);
    cudaGetSymbolAddress((void**)&hb,  g_hb);
    cudaGetSymbolAddress((void**)&f1,  g_f1);
    cudaGetSymbolAddress((void**)&f2,  g_f2);
    cudaGetSymbolAddress((void**)&qwT, g_qwT);
    cudaGetSymbolAddress((void**)&kwT, g_kwT);
    cudaGetSymbolAddress((void**)&vwT, g_vwT);
    cudaGetSymbolAddress((void**)&lwT, g_lwT);
    cudaGetSymbolAddress((void**)&w1T, g_w1T);
    cudaGetSymbolAddress((void**)&w2T, g_w2T);

    constexpr int SM128 = 2 * (2 * 128 * 48 + 2 * 128 * 48); // 49152
    constexpr int SM64  = 2 * (2 * 128 * 48 + 2 * 64 * 48);  // 36864

    float scale = 1.0f / sqrtf((float)Dn);
    dim3 tb(32, 8);

    // weight transposes
    transpose_kernel<<<dim3(Un / 32, Dn / 32, Hn), tb>>>(qw, qwT, Dn, Un);
    transpose_kernel<<<dim3(Un / 32, Dn / 32, Hn), tb>>>(kw, kwT, Dn, Un);
    transpose_kernel<<<dim3(Dn / 32, Dn / 32, Hn), tb>>>(vw, vwT, Dn, Dn);
    transpose_kernel<<<dim3(Dn / 32, (Hn * Dn) / 32, 1), tb>>>(lw, lwT, Hn * Dn, Dn);
    transpose_kernel<<<dim3(Fn / 32, Dn / 32, 1), tb>>>(w1, w1T, Dn, Fn);
    transpose_kernel<<<dim3(Dn / 32, Fn / 32, 1), tb>>>(w2, w2T, Fn, Dn);

    // Q = x @ qw[h] : M=8192, N=64, K=512
    mgemm<64, false, false><<<dim3(1, Tn / 128, Hn), 256, SM64>>>(
        x, qwT, nullptr, Q, Tn, Un, Dn, Dn, Dn, Un,
        0, 0, (long long)Un * Dn, 0, (long long)Tn * Un, 0, 1, 1.0f);
    mgemm<64, false, false><<<dim3(1, Tn / 128, Hn), 256, SM64>>>(
        x, kwT, nullptr, K, Tn, Un, Dn, Dn, Dn, Un,
        0, 0, (long long)Un * Dn, 0, (long long)Tn * Un, 0, 1, 1.0f);

    // VT[h] = vwT[h] @ x^T : M=512, N=8192, K=512
    mgemm<128, false, false><<<dim3(Tn / 128, Dn / 128, Hn), 256, SM128>>>(
        vwT, x, nullptr, VT, Dn, Tn, Dn, Dn, Dn, Tn,
        (long long)Dn * Dn, 0, 0, 0, (long long)Dn * Tn, 0, 1, 1.0f);

    // scores[h,b] = scale * Q @ K^T : M=N=1024, K=64
    mgemm<128, false, false><<<dim3(Sn / 128, Sn / 128, Hn * Bn), 256, SM128>>>(
        Q, K, nullptr, S, Sn, Sn, Un, Un, Un, Sn,
        (long long)Tn * Un, (long long)Sn * Un,
        (long long)Tn * Un, (long long)Sn * Un,
        (long long)Bn * Sn * Sn, (long long)Sn * Sn, Bn, scale);

    softmax_kernel<<<Hn * Bn * Sn, 256>>>(S);

    // attn[h,b] = P @ VT[h][:, b-slice]^T -> Ac concat [t, h*512+e]
    mgemm<128, false, false><<<dim3(Dn / 128, Sn / 128, Hn * Bn), 256, SM128>>>(
        S, VT, nullptr, Ac, Sn, Dn, Sn, Sn, Tn, Hn * Dn,
        (long long)Bn * Sn * Sn, (long long)Sn * Sn,
        (long long)Dn * Tn, (long long)Sn,
        (long long)Dn, (long long)Sn * Hn * Dn, Bn, 1.0f);

    // mha = Ac @ lw : M=8192, N=512, K=4096
    mgemm<128, false, false><<<dim3(Dn / 128, Tn / 128, 1), 256, SM128>>>(
        Ac, lwT, nullptr, mha, Tn, Dn, Hn * Dn, Hn * Dn, Hn * Dn, Dn,
        0, 0, 0, 0, 0, 0, 1, 1.0f);

    add_ln_kernel<<<Tn, 128>>>(x, mha, g1, b1v, hb);

    // f1 = relu(hb @ w1 + b1) : M=8192, N=2048, K=512
    mgemm<128, true, true><<<dim3(Fn / 128, Tn / 128, 1), 256, SM128>>>(
        hb, w1T, bb1, f1, Tn, Fn, Dn, Dn, Dn, Fn,
        0, 0, 0, 0, 0, 0, 1, 1.0f);

    // f2 = f1 @ w2 + b2 : M=8192, N=512, K=2048
    mgemm<128, true, false><<<dim3(Dn / 128, Tn / 128, 1), 256, SM128>>>(
        f1, w2T, bb2, f2, Tn, Dn, Fn, Fn, Fn, Dn,
        0, 0, 0, 0, 0, 0, 1, 1.0f);

    add_ln_kernel<<<Tn, 128>>>(hb, f2, g2, b2v, out);
}